// round 2
// baseline (speedup 1.0000x reference)
#include <cuda_runtime.h>
#include <cuda_bf16.h>
#include <cstdint>

// Problem constants (fixed by setup_inputs)
#define BATCH 2
#define LSEQ  2048
#define DMODEL 1024
#define NHEADS 16
#define DH 64
#define ROWS (BATCH * LSEQ)          // 4096
#define QKVC (3 * DMODEL)            // 3072
#define QT   64                      // queries per attention CTA
#define KT   192                     // keys per attention CTA (64 + 128)

// ---------------------------------------------------------------------------
// Scratch (device globals; no allocation at runtime)
// ---------------------------------------------------------------------------
__device__ float g_xn [ROWS * DMODEL];   // 16 MB
__device__ float g_qkv[ROWS * QKVC];     // 48 MB
__device__ float g_att[ROWS * DMODEL];   // 16 MB

// ---------------------------------------------------------------------------
// RMSNorm: one block per row (4096 rows), 256 threads, float4 path
// ---------------------------------------------------------------------------
__global__ __launch_bounds__(256) void rmsnorm_kernel(
    const float* __restrict__ x, const float* __restrict__ w,
    float* __restrict__ out)
{
    const int row = blockIdx.x;
    const float4* xr = reinterpret_cast<const float4*>(x + (size_t)row * DMODEL);
    float4 v = xr[threadIdx.x];          // 256 threads * 4 = 1024 elems
    float ss = v.x*v.x + v.y*v.y + v.z*v.z + v.w*v.w;

    #pragma unroll
    for (int o = 16; o > 0; o >>= 1)
        ss += __shfl_xor_sync(0xffffffffu, ss, o);

    __shared__ float red[8];
    const int wid = threadIdx.x >> 5, lane = threadIdx.x & 31;
    if (lane == 0) red[wid] = ss;
    __syncthreads();
    if (wid == 0) {
        float t = (lane < 8) ? red[lane] : 0.0f;
        #pragma unroll
        for (int o = 4; o > 0; o >>= 1)
            t += __shfl_xor_sync(0xffffffffu, t, o);
        if (lane == 0) red[0] = rsqrtf(t * (1.0f / DMODEL) + 1e-6f);
    }
    __syncthreads();
    const float s = red[0];
    float4 wv = reinterpret_cast<const float4*>(w)[threadIdx.x];
    float4 o4 = make_float4(v.x*s*wv.x, v.y*s*wv.y, v.z*s*wv.z, v.w*s*wv.w);
    reinterpret_cast<float4*>(out + (size_t)row * DMODEL)[threadIdx.x] = o4;
}

// ---------------------------------------------------------------------------
// SGEMM (NT): C[m,n] = sum_k A[m,k] * B[n,k] (+ skip[m,n])
// A: [M,K] row-major, B: [N,K] row-major (torch Linear weight layout).
// 128x128 tile, BK=8, 256 threads, 8x8 per-thread microtile.
// M,N,K are multiples of tile dims for all uses here (no bounds checks).
// ---------------------------------------------------------------------------
template <bool ADD_SKIP>
__global__ __launch_bounds__(256) void sgemm_nt(
    const float* __restrict__ A, const float* __restrict__ B,
    const float* __restrict__ skip, float* __restrict__ C,
    int M, int N, int K)
{
    __shared__ float As[8][128];
    __shared__ float Bs[8][128];

    const int tid  = threadIdx.x;
    const int tr   = tid >> 4;            // 0..15 (microtile row)
    const int tc   = tid & 15;            // 0..15 (microtile col)
    const int row0 = blockIdx.y * 128;
    const int col0 = blockIdx.x * 128;

    const int lr = tid >> 1;              // 0..127 : load row
    const int lc = (tid & 1) << 2;        // 0 or 4 : load col (float4)
    const float* Ap = A + (size_t)(row0 + lr) * K + lc;
    const float* Bp = B + (size_t)(col0 + lr) * K + lc;

    float acc[8][8];
    #pragma unroll
    for (int i = 0; i < 8; i++)
        #pragma unroll
        for (int j = 0; j < 8; j++) acc[i][j] = 0.0f;

    for (int k0 = 0; k0 < K; k0 += 8) {
        float4 a4 = *reinterpret_cast<const float4*>(Ap + k0);
        float4 b4 = *reinterpret_cast<const float4*>(Bp + k0);
        As[lc+0][lr] = a4.x; As[lc+1][lr] = a4.y; As[lc+2][lr] = a4.z; As[lc+3][lr] = a4.w;
        Bs[lc+0][lr] = b4.x; Bs[lc+1][lr] = b4.y; Bs[lc+2][lr] = b4.z; Bs[lc+3][lr] = b4.w;
        __syncthreads();
        #pragma unroll
        for (int kk = 0; kk < 8; kk++) {
            float4 a0 = *reinterpret_cast<const float4*>(&As[kk][tr*8]);
            float4 a1 = *reinterpret_cast<const float4*>(&As[kk][tr*8+4]);
            float4 b0 = *reinterpret_cast<const float4*>(&Bs[kk][tc*8]);
            float4 b1 = *reinterpret_cast<const float4*>(&Bs[kk][tc*8+4]);
            float af[8] = {a0.x,a0.y,a0.z,a0.w,a1.x,a1.y,a1.z,a1.w};
            float bf[8] = {b0.x,b0.y,b0.z,b0.w,b1.x,b1.y,b1.z,b1.w};
            #pragma unroll
            for (int i = 0; i < 8; i++)
                #pragma unroll
                for (int j = 0; j < 8; j++)
                    acc[i][j] += af[i] * bf[j];
        }
        __syncthreads();
    }

    #pragma unroll
    for (int i = 0; i < 8; i++) {
        const size_t off = (size_t)(row0 + tr*8 + i) * N + col0 + tc*8;
        float4 c0 = make_float4(acc[i][0], acc[i][1], acc[i][2], acc[i][3]);
        float4 c1 = make_float4(acc[i][4], acc[i][5], acc[i][6], acc[i][7]);
        if (ADD_SKIP) {
            float4 s0 = *reinterpret_cast<const float4*>(skip + off);
            float4 s1 = *reinterpret_cast<const float4*>(skip + off + 4);
            c0.x += s0.x; c0.y += s0.y; c0.z += s0.z; c0.w += s0.w;
            c1.x += s1.x; c1.y += s1.y; c1.z += s1.z; c1.w += s1.w;
        }
        *reinterpret_cast<float4*>(C + off)     = c0;
        *reinterpret_cast<float4*>(C + off + 4) = c1;
    }
}

// ---------------------------------------------------------------------------
// Banded attention. Grid: (L/QT, H, B), 256 threads.
// Each CTA: 64 queries of one (b,h). Keys j=0..191 map to kglob = q0-64+j.
// 4 threads per query (part = tid&3); each owns 48 keys.
// K tile staged in 48 KB static smem; V streamed from global (L1/L2-resident).
// ---------------------------------------------------------------------------
__global__ __launch_bounds__(256) void attn_kernel(
    const float* __restrict__ qkv, float* __restrict__ att)
{
    __shared__ float Ks[KT * DH];        // exactly 48 KB

    const int qt = blockIdx.x, h = blockIdx.y, b = blockIdx.z;
    const int q0 = qt * QT;
    const int k0 = q0 - 64;
    const int tid  = threadIdx.x;
    const int part = tid & 3;
    const int q    = tid >> 2;           // 0..63
    const size_t base = (size_t)b * LSEQ * QKVC;

    // cooperative K-tile load (zero-fill out-of-range rows)
    for (int idx = tid; idx < KT * (DH/4); idx += 256) {
        const int j = idx >> 4, dc = idx & 15;
        const int kg = k0 + j;
        float4 val = make_float4(0.f, 0.f, 0.f, 0.f);
        if (kg >= 0 && kg < LSEQ)
            val = *reinterpret_cast<const float4*>(
                qkv + base + (size_t)kg * QKVC + DMODEL + h*DH + dc*4);
        *reinterpret_cast<float4*>(&Ks[j*DH + dc*4]) = val;
    }
    __syncthreads();

    // q row into registers (4 threads share the same row; L1 broadcast)
    float qf[DH];
    {
        const float4* qp = reinterpret_cast<const float4*>(
            qkv + base + (size_t)(q0 + q) * QKVC + h*DH);
        #pragma unroll
        for (int dc = 0; dc < 16; dc++) {
            float4 v = qp[dc];
            qf[dc*4+0] = v.x; qf[dc*4+1] = v.y; qf[dc*4+2] = v.z; qf[dc*4+3] = v.w;
        }
    }

    // scores for this thread's 48 keys
    float p[48];
    float mx = -1e30f;
    #pragma unroll
    for (int jj = 0; jj < 48; jj++) {
        const int j = part * 48 + jj;
        float s = 0.0f;
        const float4* kp = reinterpret_cast<const float4*>(&Ks[j*DH]);
        #pragma unroll
        for (int dc = 0; dc < 16; dc++) {
            float4 kv = kp[dc];
            s += qf[dc*4+0]*kv.x + qf[dc*4+1]*kv.y
               + qf[dc*4+2]*kv.z + qf[dc*4+3]*kv.w;
        }
        s *= 0.125f;                     // 1/sqrt(64)
        const int kg = k0 + j;
        const bool valid = (j >= q) && (j <= q + 128) && (kg >= 0) && (kg < LSEQ);
        s = valid ? s : -1e30f;
        p[jj] = s;
        mx = fmaxf(mx, s);
    }
    // row max / sum across the 4 partner lanes (lanes differ in bits 0..1)
    mx = fmaxf(mx, __shfl_xor_sync(0xffffffffu, mx, 1));
    mx = fmaxf(mx, __shfl_xor_sync(0xffffffffu, mx, 2));
    float sum = 0.0f;
    #pragma unroll
    for (int jj = 0; jj < 48; jj++) {
        const float e = __expf(p[jj] - mx);   // masked entries underflow to 0
        p[jj] = e;
        sum += e;
    }
    sum += __shfl_xor_sync(0xffffffffu, sum, 1);
    sum += __shfl_xor_sync(0xffffffffu, sum, 2);
    const float inv = 1.0f / sum;             // self-key always valid => sum > 0

    // P @ V (V streamed from global; clamped address + p==0 kills OOB rows)
    float acc[DH];
    #pragma unroll
    for (int d = 0; d < DH; d++) acc[d] = 0.0f;
    #pragma unroll
    for (int jj = 0; jj < 48; jj++) {
        const float pv = p[jj] * inv;
        int kg = k0 + part * 48 + jj;
        kg = (kg < 0) ? 0 : ((kg >= LSEQ) ? (LSEQ - 1) : kg);
        const float4* vp = reinterpret_cast<const float4*>(
            qkv + base + (size_t)kg * QKVC + 2*DMODEL + h*DH);
        #pragma unroll
        for (int dc = 0; dc < 16; dc++) {
            float4 v = vp[dc];
            acc[dc*4+0] += pv * v.x; acc[dc*4+1] += pv * v.y;
            acc[dc*4+2] += pv * v.z; acc[dc*4+3] += pv * v.w;
        }
    }
    // reduce partials across the 4 partner lanes
    #pragma unroll
    for (int d = 0; d < DH; d++) {
        float r = acc[d];
        r += __shfl_xor_sync(0xffffffffu, r, 1);
        r += __shfl_xor_sync(0xffffffffu, r, 2);
        acc[d] = r;
    }
    if (part == 0) {
        float* orow = att + ((size_t)b * LSEQ + q0 + q) * DMODEL + h*DH;
        #pragma unroll
        for (int dc = 0; dc < 16; dc++)
            *reinterpret_cast<float4*>(&orow[dc*4]) =
                make_float4(acc[dc*4+0], acc[dc*4+1], acc[dc*4+2], acc[dc*4+3]);
    }
}

// ---------------------------------------------------------------------------
// Launch
// ---------------------------------------------------------------------------
extern "C" void kernel_launch(void* const* d_in, const int* in_sizes, int n_in,
                              void* d_out, int out_size)
{
    const float* x      = (const float*)d_in[0];
    const float* w_norm = (const float*)d_in[1];
    const float* w_qkv  = (const float*)d_in[2];
    const float* w_out  = (const float*)d_in[3];
    float* out = (float*)d_out;

    float *xn_p, *qkv_p, *att_p;
    cudaGetSymbolAddress((void**)&xn_p,  g_xn);
    cudaGetSymbolAddress((void**)&qkv_p, g_qkv);
    cudaGetSymbolAddress((void**)&att_p, g_att);

    // 1) RMSNorm
    rmsnorm_kernel<<<ROWS, 256>>>(x, w_norm, xn_p);

    // 2) QKV = xn @ w_qkv^T : [4096,3072]
    {
        dim3 grid(QKVC / 128, ROWS / 128);   // (24, 32)
        sgemm_nt<false><<<grid, 256>>>(xn_p, w_qkv, nullptr, qkv_p,
                                       ROWS, QKVC, DMODEL);
    }

    // 3) Banded attention
    {
        dim3 grid(LSEQ / QT, NHEADS, BATCH); // (32, 16, 2)
        attn_kernel<<<grid, 256>>>(qkv_p, att_p);
    }

    // 4) out = att @ w_out^T + x : [4096,1024]
    {
        dim3 grid(DMODEL / 128, ROWS / 128); // (8, 32)
        sgemm_nt<true><<<grid, 256>>>(att_p, w_out, x, out,
                                      ROWS, DMODEL, DMODEL);
    }
}